// round 12
// baseline (speedup 1.0000x reference)
#include <cuda_runtime.h>
#include <stdint.h>

#define WIN 32
#define NPX 1024
#define NH 992
#define NEDGE 1984
#define SORTN 2048
#define NTHREADS 256
#define FULLM 0xffffffffu
#define DONE_BIT (1 << 30)

#define BARSYNC(id) asm volatile("bar.sync %0, %1;" :: "r"(id), "r"(128) : "memory")

struct Smem {
    float pred[NPX];
    unsigned char tvi[NPX];
    unsigned rowmask[32];          // dilated mask bits, 1 = masked
    unsigned par32[NPX];           // CC labeling union-find (u32 for atomicCAS)
    unsigned short lab[NPX];
    unsigned char pres[NPX];
    unsigned short cid[NPX];
    unsigned char eflags[NEDGE];
    float w0[NEDGE];
    float w1[NEDGE];
    unsigned short order0[NEDGE];
    unsigned short order1[NEDGE];
    unsigned short parent[2][NPX];
    unsigned sizTot[2][NPX];       // (siz<<16) | tot, one load per root
    // packed merge log: sa | sb<<11 | rs<<22 | rl<<32 | e<<42
    unsigned long long mlog[2][NPX];
    unsigned batch[2][32];         // ra | rb<<10 | e<<20
    int logCnt[2];
    int Lval;
    int wsum[8];
    int wpre[8];
    float red[NTHREADS];
    // big[r]: sorts = u64 sortbuf (16KB of 64KB); replay = u16 cnt[NPX][32]
    alignas(16) unsigned char big[2][65536];
};

__device__ __forceinline__ void edge_nodes(int e, int& n1, int& n2) {
    if (e < NH) {
        int r = e / 31;
        int c = e - r * 31;
        n1 = (r << 5) + c;
        n2 = n1 + 1;
    } else {
        n1 = e - NH;
        n2 = n1 + 32;
    }
}

__device__ __forceinline__ int uf_find(unsigned short* par, int x) {
    while (par[x] != x) {
        par[x] = par[par[x]];
        x = par[x];
    }
    return x;
}

// ---- lock-free CC union-find (shared mem) ----
// Path-halving find: writes only par[x] = grandparent(x), NEVER writes to a
// root, so committed unions can never be resurrected by a racing find.
__device__ __forceinline__ unsigned cc_find(unsigned* par_, unsigned x) {
    volatile unsigned* par = par_;
    for (;;) {
        unsigned p = par[x];
        if (p == x) return x;
        unsigned g = par[p];
        if (g == p) return p;      // p is root
        par[x] = g;                // halve (g is an ancestor, g < x)
        x = g;
    }
}

__device__ __forceinline__ void cc_union(unsigned* par, unsigned a, unsigned b) {
    a = cc_find(par, a);
    b = cc_find(par, b);
    while (a != b) {
        if (a < b) { unsigned t = a; a = b; b = t; }   // ensure a > b
        unsigned old = atomicCAS(&par[a], a, b);
        if (old == a) return;
        a = cc_find(par, old);
        b = cc_find(par, b);
    }
}

// Bitonic sort over SORTN u64 keys with 128 threads; named barrier barid.
__device__ void bitonic_sort_half(unsigned long long* buf, int t, int barid) {
    for (int k = 2; k <= SORTN; k <<= 1) {
        for (int jj = k >> 1; jj > 0; jj >>= 1) {
            for (int i = t; i < SORTN; i += 128) {
                int p = i ^ jj;
                if (p > i) {
                    unsigned long long a = buf[i];
                    unsigned long long b = buf[p];
                    bool up = ((i & k) == 0);
                    if ((a > b) == up) { buf[i] = b; buf[p] = a; }
                }
            }
            BARSYNC(barid);
        }
    }
}

// Warp-cooperative speculative Kruskal (producer), shfl-free serial section.
// Per batch: 32 parallel finds -> dump (ra,rb,e) to smem -> lane 0 runs the
// serial merge loop with plain LDS loads and packed size/log entries.
__device__ void kruskal_warp(Smem* s, int run, const unsigned short* order) {
    unsigned short* par = s->parent[run];
    unsigned* st = s->sizTot[run];
    unsigned long long* lg = s->mlog[run];
    unsigned* batch = s->batch[run];
    volatile int* vc = &s->logCnt[run];

    const int lane = threadIdx.x & 31;
    int nlog = 0;

    for (int base = 0; base < NEDGE; base += 32) {
        int e = order[base + lane];
        int n1, n2;
        edge_nodes(e, n1, n2);
        int ra = uf_find(par, n1);
        int rb = uf_find(par, n2);
        // "connected in snapshot" is monotone => safe to drop those edges.
        unsigned alive = __ballot_sync(FULLM, ra != rb);
        batch[lane] = (unsigned)ra | ((unsigned)rb << 10) | ((unsigned)e << 20);
        __syncwarp();
        if (lane == 0 && alive) {
            // prefetch first entry
            int i = __ffs(alive) - 1;
            alive &= alive - 1;
            unsigned w = batch[i];
            for (;;) {
                unsigned wcur = w;
                bool more = (alive != 0);
                if (more) {                      // prefetch next entry
                    int i2 = __ffs(alive) - 1;
                    alive &= alive - 1;
                    w = batch[i2];
                }
                int rai = wcur & 1023;
                int rbi = (wcur >> 10) & 1023;
                int ei  = wcur >> 20;
                rai = uf_find(par, rai);         // short re-find (<=2 hops)
                rbi = uf_find(par, rbi);
                if (rai != rbi) {
                    unsigned pa = st[rai], pb = st[rbi];
                    int rs, rl;
                    unsigned ps, pl;
                    if ((pa >> 16) <= (pb >> 16)) { rs = rai; rl = rbi; ps = pa; pl = pb; }
                    else                          { rs = rbi; rl = rai; ps = pb; pl = pa; }
                    unsigned sa = ps & 0xffffu, sb = pl & 0xffffu;
                    par[rs] = (unsigned short)rl;
                    st[rl] = (((pa >> 16) + (pb >> 16)) << 16) | (sa + sb);
                    lg[nlog] = (unsigned long long)sa
                             | ((unsigned long long)sb << 11)
                             | ((unsigned long long)rs << 22)
                             | ((unsigned long long)rl << 32)
                             | ((unsigned long long)ei << 42);
                    nlog++;
                }
                if (!more) break;
            }
            __threadfence_block();
            *vc = nlog;                          // release publish
        }
        __syncwarp();
    }
    if (lane == 0) {
        __threadfence_block();
        *vc = nlog | DONE_BIT;
    }
}

// Streaming replay consumer (pass 0) + extra passes for L > 32.
__device__ void replay_consumer(Smem* s, int run, int L, bool pos) {
    const int lane = threadIdx.x & 31;
    unsigned short (*cnt)[32] = (unsigned short(*)[32])(s->big[run]);
    float* w = pos ? s->w1 : s->w0;
    volatile int* vc = &s->logCnt[run];
    unsigned long long* lg = s->mlog[run];

    int processed = 0, avail = 0;
    bool done = false;
    int nlog = 0;
    for (;;) {
        if (processed >= avail) {
            if (done) break;
            int v = *vc;                 // broadcast LDS
            int na = v & ~DONE_BIT;
            if (v & DONE_BIT) { done = true; nlog = na; }
            if (na > avail) {
                avail = na;
                __threadfence_block();   // acquire: order log reads after count
            }
            if (processed >= avail) {
                if (done) break;
                continue;
            }
        }
        int k = processed++;
        unsigned long long v64 = lg[k];  // one LDS.64 broadcast
        int sa = (int)(v64 & 0x7ffu);
        int sb = (int)((v64 >> 11) & 0x7ffu);
        int rs = (int)((v64 >> 22) & 0x3ffu);
        int rl = (int)((v64 >> 32) & 0x3ffu);
        if (sa == 0) continue;
        if (sb == 0) { cnt[rl][lane] = cnt[rs][lane]; continue; }
        unsigned a = cnt[rs][lane];
        unsigned b = cnt[rl][lane];
        unsigned same = __reduce_add_sync(FULLM, a * b);
        cnt[rl][lane] = (unsigned short)(a + b);
        if (lane == 0) {
            int e = (int)(v64 >> 42);
            w[e] = pos ? (float)same : (float)(sa * sb) - (float)same;
        }
    }

    // extra label chunks (rare: L > 32)
    for (int p = 1; p * 32 < L; p++) {
        unsigned* c32 = (unsigned*)cnt;
        for (int i = lane; i < NPX * 16; i += 32) c32[i] = 0;
        __syncwarp();
        for (int px = lane; px < NPX; px += 32) {
            int l = s->lab[px];
            if (l) {
                int c = (int)s->cid[l - 1] - p * 32;
                if (c >= 0 && c < 32) cnt[px][c] = 1;
            }
        }
        __syncwarp();
        for (int k = 0; k < nlog; k++) {
            unsigned long long v64 = lg[k];
            int sa = (int)(v64 & 0x7ffu);
            int sb = (int)((v64 >> 11) & 0x7ffu);
            int rs = (int)((v64 >> 22) & 0x3ffu);
            int rl = (int)((v64 >> 32) & 0x3ffu);
            if (sa == 0) continue;
            if (sb == 0) { cnt[rl][lane] = cnt[rs][lane]; continue; }
            unsigned a = cnt[rs][lane];
            unsigned b = cnt[rl][lane];
            unsigned same = __reduce_add_sync(FULLM, a * b);
            cnt[rl][lane] = (unsigned short)(a + b);
            if (lane == 0) {
                int e = (int)(v64 >> 42);
                if (pos) w[e] += (float)same;
                else     w[e] -= (float)same;
            }
        }
        __syncwarp();
    }
}

__device__ float block_reduce(Smem* s, float v) {
    int tid = threadIdx.x;
    s->red[tid] = v;
    __syncthreads();
    for (int off = NTHREADS / 2; off > 0; off >>= 1) {
        if (tid < off) s->red[tid] += s->red[tid + off];
        __syncthreads();
    }
    float r = s->red[0];
    __syncthreads();
    return r;
}

__global__ void __launch_bounds__(NTHREADS, 1)
zero_kernel(float* out, int n) {
    int i = blockIdx.x * blockDim.x + threadIdx.x;
    if (i < n) out[i] = 0.0f;
}

__global__ void __launch_bounds__(NTHREADS, 1)
malis_kernel(const float* __restrict__ pred,
             const float* __restrict__ target,
             const float* __restrict__ lrn_p,
             const float* __restrict__ lrp_p,
             float* __restrict__ out,
             int HW) {
    extern __shared__ char smem_raw[];
    Smem* s = (Smem*)smem_raw;
    const int tid = threadIdx.x;
    const int lane = tid & 31;

    int wpr = HW / WIN;
    int winPerImg = wpr * wpr;
    int b = blockIdx.x / winPerImg;
    int rem = blockIdx.x - b * winPerImg;
    int k = rem / wpr;
    int j = rem - k * wpr;
    int y0 = k * WIN, x0 = j * WIN;

    const float* pb = pred + (size_t)b * HW * HW;
    const float* tb = target + (size_t)b * HW * HW;

    // ---- 1. load tile; build zero-mask row bits via ballot ----
    for (int px = tid; px < NPX; px += NTHREADS) {
        int y = px >> 5, x = px & 31;
        float pv = pb[(y0 + y) * HW + (x0 + x)];
        float tv = tb[(y0 + y) * HW + (x0 + x)];
        s->pred[px] = pv;
        s->tvi[px] = (unsigned char)tv;            // ints 0..25, exact
        unsigned zb = __ballot_sync(FULLM, tv == 0.0f);
        if (lane == 0) s->rowmask[y] = zb;         // stride 256 => lane == x
    }
    __syncthreads();

    // ---- 2. dilate 5x in registers (warp 0, shfl across rows) ----
    if (tid < 32) {
        unsigned r = s->rowmask[tid];
        for (int it = 0; it < 5; it++) {
            unsigned up = __shfl_up_sync(FULLM, r, 1);
            unsigned dn = __shfl_down_sync(FULLM, r, 1);
            if (tid == 0) up = 0;
            if (tid == 31) dn = 0;
            r = r | (r << 1) | (r >> 1) | up | dn;
        }
        s->rowmask[tid] = r;
    }
    for (int px = tid; px < NPX; px += NTHREADS) s->par32[px] = (unsigned)px;
    __syncthreads();

    // ---- 3. 8-connected CC via lock-free union-find ----
    for (int px = tid; px < NPX; px += NTHREADS) {
        int y = px >> 5, x = px & 31;
        unsigned my = s->rowmask[y];
        if ((my >> x) & 1) continue;               // masked
        if (x < 31 && !((my >> (x + 1)) & 1)) cc_union(s->par32, px, px + 1);
        if (y < 31) {
            unsigned nx = s->rowmask[y + 1];
            if (!((nx >> x) & 1))                 cc_union(s->par32, px, px + 32);
            if (x < 31 && !((nx >> (x + 1)) & 1)) cc_union(s->par32, px, px + 33);
            if (x > 0  && !((nx >> (x - 1)) & 1)) cc_union(s->par32, px, px + 31);
        }
    }
    __syncthreads();
    for (int px = tid; px < NPX; px += NTHREADS) {
        int y = px >> 5, x = px & 31;
        unsigned my = s->rowmask[y];
        s->lab[px] = ((my >> x) & 1) ? 0
                   : (unsigned short)(cc_find(s->par32, px) + 1);
    }
    __syncthreads();

    // ---- 4. compact label ids ----
    for (int px = tid; px < NPX; px += NTHREADS) s->pres[px] = 0;
    __syncthreads();
    for (int px = tid; px < NPX; px += NTHREADS) {
        int l = s->lab[px];
        if (l) s->pres[l - 1] = 1;
    }
    __syncthreads();
    {
        int i0 = 4 * tid;
        int b0 = s->pres[i0], b1 = s->pres[i0 + 1];
        int b2 = s->pres[i0 + 2], b3 = s->pres[i0 + 3];
        int sum4 = b0 + b1 + b2 + b3;
        int incl = sum4;
        for (int off = 1; off < 32; off <<= 1) {
            int v = __shfl_up_sync(FULLM, incl, off);
            if (lane >= off) incl += v;
        }
        if (lane == 31) s->wsum[tid >> 5] = incl;
        __syncthreads();
        if (tid < 8) {
            int v = s->wsum[tid];
            int inc2 = v;
            for (int off = 1; off < 8; off <<= 1) {
                int t2 = __shfl_up_sync(0xffu, inc2, off);
                if (tid >= off) inc2 += t2;
            }
            s->wpre[tid] = inc2 - v;
            if (tid == 7) s->Lval = inc2;
        }
        __syncthreads();
        int pre = s->wpre[tid >> 5] + (incl - sum4);
        s->cid[i0]     = (unsigned short)pre;
        s->cid[i0 + 1] = (unsigned short)(pre + b0);
        s->cid[i0 + 2] = (unsigned short)(pre + b0 + b1);
        s->cid[i0 + 3] = (unsigned short)(pre + b0 + b1 + b2);
    }

    // ---- 5. edge flags, weight init, Kruskal union-find init ----
    for (int e = tid; e < NEDGE; e += NTHREADS) {
        int n1, n2;
        edge_nodes(e, n1, n2);
        int gtc = (int)s->tvi[n1] + (int)s->tvi[n2];
        unsigned char f = 0;
        if (gtc < 10)  f |= 1;
        if (gtc >= 20) f |= 2;
        if (gtc > 20)  f |= 4;
        s->eflags[e] = f;
        s->w0[e] = 0.0f;
        s->w1[e] = 0.0f;
    }
    for (int px = tid; px < NPX; px += NTHREADS) {
        unsigned short L = s->lab[px];
        unsigned stv = (1u << 16) | (L ? 1u : 0u);
        for (int r = 0; r < 2; r++) {
            s->parent[r][px] = (unsigned short)px;
            s->sizTot[r][px] = stv;
        }
    }
    if (tid < 2) s->logCnt[tid] = 0;
    __syncthreads();

    // ---- 6. two concurrent bitonic sorts (half-block each) ----
    {
        int half = tid >> 7;
        int t128 = tid & 127;
        int barid = half + 1;
        unsigned long long* sb = (unsigned long long*)(s->big[half]);
        for (int i = t128; i < SORTN; i += 128) {
            unsigned long long key;
            if (i < NEDGE) {
                int n1, n2;
                edge_nodes(i, n1, n2);
                float c;
                if (half == 0) {
                    c = s->pred[n1] + s->pred[n2];
                    if (s->eflags[i] & 4) c = 20.0f;
                } else {
                    c = (s->eflags[i] & 1) ? 0.0f
                                           : s->pred[n1] + s->pred[n2];
                }
                // nonneg floats: bit-monotone; ascending u64 =
                // descending cost, ties by ascending index.
                key = (((unsigned long long)(~__float_as_uint(c))) << 32)
                      | (unsigned)i;
            } else {
                key = ~0ULL;
            }
            sb[i] = key;
        }
        BARSYNC(barid);
        bitonic_sort_half(sb, t128, barid);
        unsigned short* ord = half ? s->order1 : s->order0;
        for (int i = t128; i < NEDGE; i += 128)
            ord[i] = (unsigned short)(sb[i] & 0xffffu);
    }
    __syncthreads();

    // ---- 7. zero cnt matrices (alias sortbuf) + scatter labeled pixels ----
    {
        unsigned* c32 = (unsigned*)s->big;
        for (int i = tid; i < 2 * 65536 / 4; i += NTHREADS) c32[i] = 0;
    }
    __syncthreads();
    {
        unsigned short (*c0)[32] = (unsigned short(*)[32])(s->big[0]);
        unsigned short (*c1)[32] = (unsigned short(*)[32])(s->big[1]);
        for (int px = tid; px < NPX; px += NTHREADS) {
            int l = s->lab[px];
            if (l) {
                int c = s->cid[l - 1];
                if (c < 32) { c0[px][c] = 1; c1[px][c] = 1; }
            }
        }
    }
    __syncthreads();

    // ---- 8. pipelined Kruskal (producers: warps 0,1) + replay (consumers: 2,3) ----
    {
        int wid = tid >> 5;
        int L = s->Lval;
        if      (wid == 0) kruskal_warp(s, 0, s->order0);
        else if (wid == 1) kruskal_warp(s, 1, s->order1);
        else if (wid == 2) replay_consumer(s, 0, L, false);
        else if (wid == 3) replay_consumer(s, 1, L, true);
    }
    __syncthreads();

    // ---- 9. normalize, mask, gather to nodes, loss ----
    float vn = 0.0f, vp = 0.0f;
    for (int e = tid; e < NEDGE; e += NTHREADS) {
        vn += s->w0[e];
        vp += s->w1[e];
    }
    float sn = block_reduce(s, vn);
    float sp = block_reduce(s, vp);

    for (int e = tid; e < NEDGE; e += NTHREADS) {
        unsigned char f = s->eflags[e];
        float a = s->w0[e];
        if (sn > 0.0f) a /= sn;
        s->w0[e] = (f & 1) ? a : 0.0f;
        float bb = s->w1[e];
        if (sp > 0.0f) bb /= sp;
        s->w1[e] = (f & 2) ? bb : 0.0f;
    }
    __syncthreads();

    float lrn = lrn_p[0];
    float lrp = lrp_p[0];
    float acc = 0.0f;
    for (int px = tid; px < NPX; px += NTHREADS) {
        int y = px >> 5, x = px & 31;
        float wn = 0.0f, wp = 0.0f;
        if (x > 0)  { int e = y * 31 + x - 1; wn += s->w0[e]; wp += s->w1[e]; }
        if (x < 31) { int e = y * 31 + x;     wn += s->w0[e]; wp += s->w1[e]; }
        if (y > 0)  { int e = NH + px - 32;   wn += s->w0[e]; wp += s->w1[e]; }
        if (y < 31) { int e = NH + px;        wn += s->w0[e]; wp += s->w1[e]; }
        float p = s->pred[px];
        float d = 20.0f - p;
        acc += lrn * p * p * wn + lrp * d * d * wp;
    }
    float total = block_reduce(s, acc);
    if (tid == 0) atomicAdd(out, total);
}

extern "C" void kernel_launch(void* const* d_in, const int* in_sizes, int n_in,
                              void* d_out, int out_size) {
    const float* pred   = (const float*)d_in[0];
    const float* target = (const float*)d_in[1];
    const float* lrn    = (const float*)d_in[2];
    const float* lrp    = (const float*)d_in[3];
    float* out = (float*)d_out;

    const int HW = 256;
    int B = in_sizes[0] / (HW * HW);
    int nblocks = B * (HW / WIN) * (HW / WIN);

    cudaFuncSetAttribute(malis_kernel,
                         cudaFuncAttributeMaxDynamicSharedMemorySize,
                         (int)sizeof(Smem));

    zero_kernel<<<(out_size + NTHREADS - 1) / NTHREADS, NTHREADS>>>(out, out_size);
    malis_kernel<<<nblocks, NTHREADS, sizeof(Smem)>>>(pred, target, lrn, lrp, out, HW);
}

// round 13
// speedup vs baseline: 1.0024x; 1.0024x over previous
#include <cuda_runtime.h>
#include <stdint.h>

#define WIN 32
#define NPX 1024
#define NH 992
#define NEDGE 1984
#define SORTN 2048
#define NTHREADS 256
#define FULLM 0xffffffffu
#define DONE_BIT (1 << 30)

#define BARSYNC(id) asm volatile("bar.sync %0, %1;" :: "r"(id), "r"(128) : "memory")

struct Smem {
    float pred[NPX];
    unsigned char tvi[NPX];
    unsigned rowmask[32];          // dilated mask bits, 1 = masked
    unsigned par32[NPX];           // CC labeling union-find (u32 for atomicCAS)
    unsigned short lab[NPX];
    unsigned char pres[NPX];
    unsigned short cid[NPX];
    unsigned char eflags[NEDGE];
    float w0[NEDGE];
    float w1[NEDGE];
    unsigned short order0[NEDGE];
    unsigned short order1[NEDGE];
    unsigned short parent[2][NPX];
    unsigned sizTot[2][NPX];       // (siz<<16) | tot, one load per root
    // packed merge log: sa | sb<<11 | rs<<22 | rl<<32 | e<<42
    unsigned long long mlog[2][NPX];
    unsigned batch[2][32];         // ra | rb<<10 | e<<20
    int logCnt[2];
    int Lval;
    int wsum[8];
    int wpre[8];
    float red[NTHREADS];
    // big[r]: sorts = u64 sortbuf (16KB of 64KB); replay = u16 cnt[NPX][32]
    alignas(16) unsigned char big[2][65536];
};

__device__ __forceinline__ void edge_nodes(int e, int& n1, int& n2) {
    if (e < NH) {
        int r = e / 31;
        int c = e - r * 31;
        n1 = (r << 5) + c;
        n2 = n1 + 1;
    } else {
        n1 = e - NH;
        n2 = n1 + 32;
    }
}

__device__ __forceinline__ int uf_find(unsigned short* par, int x) {
    while (par[x] != x) {
        par[x] = par[par[x]];
        x = par[x];
    }
    return x;
}

// ---- lock-free CC union-find (shared mem) ----
// Path-halving find: writes only par[x] = grandparent(x), NEVER writes to a
// root, so committed unions can never be resurrected by a racing find.
__device__ __forceinline__ unsigned cc_find(unsigned* par_, unsigned x) {
    volatile unsigned* par = par_;
    for (;;) {
        unsigned p = par[x];
        if (p == x) return x;
        unsigned g = par[p];
        if (g == p) return p;      // p is root
        par[x] = g;                // halve (g is an ancestor, g < x)
        x = g;
    }
}

__device__ __forceinline__ void cc_union(unsigned* par, unsigned a, unsigned b) {
    a = cc_find(par, a);
    b = cc_find(par, b);
    while (a != b) {
        if (a < b) { unsigned t = a; a = b; b = t; }   // ensure a > b
        unsigned old = atomicCAS(&par[a], a, b);
        if (old == a) return;
        a = cc_find(par, old);
        b = cc_find(par, b);
    }
}

// Bitonic sort over SORTN u64 keys with 128 threads; named barrier barid.
__device__ void bitonic_sort_half(unsigned long long* buf, int t, int barid) {
    for (int k = 2; k <= SORTN; k <<= 1) {
        for (int jj = k >> 1; jj > 0; jj >>= 1) {
            for (int i = t; i < SORTN; i += 128) {
                int p = i ^ jj;
                if (p > i) {
                    unsigned long long a = buf[i];
                    unsigned long long b = buf[p];
                    bool up = ((i & k) == 0);
                    if ((a > b) == up) { buf[i] = b; buf[p] = a; }
                }
            }
            BARSYNC(barid);
        }
    }
}

// Warp-cooperative speculative Kruskal (producer), shfl-free serial section.
// Per batch: 32 parallel finds -> dump (ra,rb,e) to smem -> lane 0 runs the
// serial merge loop with plain LDS loads and packed size/log entries.
__device__ void kruskal_warp(Smem* s, int run, const unsigned short* order) {
    unsigned short* par = s->parent[run];
    unsigned* st = s->sizTot[run];
    unsigned long long* lg = s->mlog[run];
    unsigned* batch = s->batch[run];
    volatile int* vc = &s->logCnt[run];

    const int lane = threadIdx.x & 31;
    int nlog = 0;

    for (int base = 0; base < NEDGE; base += 32) {
        int e = order[base + lane];
        int n1, n2;
        edge_nodes(e, n1, n2);
        int ra = uf_find(par, n1);
        int rb = uf_find(par, n2);
        // "connected in snapshot" is monotone => safe to drop those edges.
        unsigned alive = __ballot_sync(FULLM, ra != rb);
        batch[lane] = (unsigned)ra | ((unsigned)rb << 10) | ((unsigned)e << 20);
        __syncwarp();
        if (lane == 0 && alive) {
            // prefetch first entry
            int i = __ffs(alive) - 1;
            alive &= alive - 1;
            unsigned w = batch[i];
            for (;;) {
                unsigned wcur = w;
                bool more = (alive != 0);
                if (more) {                      // prefetch next entry
                    int i2 = __ffs(alive) - 1;
                    alive &= alive - 1;
                    w = batch[i2];
                }
                int rai = wcur & 1023;
                int rbi = (wcur >> 10) & 1023;
                int ei  = wcur >> 20;
                rai = uf_find(par, rai);         // short re-find (<=2 hops)
                rbi = uf_find(par, rbi);
                if (rai != rbi) {
                    unsigned pa = st[rai], pb = st[rbi];
                    int rs, rl;
                    unsigned ps, pl;
                    if ((pa >> 16) <= (pb >> 16)) { rs = rai; rl = rbi; ps = pa; pl = pb; }
                    else                          { rs = rbi; rl = rai; ps = pb; pl = pa; }
                    unsigned sa = ps & 0xffffu, sb = pl & 0xffffu;
                    par[rs] = (unsigned short)rl;
                    st[rl] = (((pa >> 16) + (pb >> 16)) << 16) | (sa + sb);
                    lg[nlog] = (unsigned long long)sa
                             | ((unsigned long long)sb << 11)
                             | ((unsigned long long)rs << 22)
                             | ((unsigned long long)rl << 32)
                             | ((unsigned long long)ei << 42);
                    nlog++;
                }
                if (!more) break;
            }
            __threadfence_block();
            *vc = nlog;                          // release publish
        }
        __syncwarp();
    }
    if (lane == 0) {
        __threadfence_block();
        *vc = nlog | DONE_BIT;
    }
}

// Streaming replay consumer (pass 0) + extra passes for L > 32.
__device__ void replay_consumer(Smem* s, int run, int L, bool pos) {
    const int lane = threadIdx.x & 31;
    unsigned short (*cnt)[32] = (unsigned short(*)[32])(s->big[run]);
    float* w = pos ? s->w1 : s->w0;
    volatile int* vc = &s->logCnt[run];
    unsigned long long* lg = s->mlog[run];

    int processed = 0, avail = 0;
    bool done = false;
    int nlog = 0;
    for (;;) {
        if (processed >= avail) {
            if (done) break;
            int v = *vc;                 // broadcast LDS
            int na = v & ~DONE_BIT;
            if (v & DONE_BIT) { done = true; nlog = na; }
            if (na > avail) {
                avail = na;
                __threadfence_block();   // acquire: order log reads after count
            }
            if (processed >= avail) {
                if (done) break;
                continue;
            }
        }
        int k = processed++;
        unsigned long long v64 = lg[k];  // one LDS.64 broadcast
        int sa = (int)(v64 & 0x7ffu);
        int sb = (int)((v64 >> 11) & 0x7ffu);
        int rs = (int)((v64 >> 22) & 0x3ffu);
        int rl = (int)((v64 >> 32) & 0x3ffu);
        if (sa == 0) continue;
        if (sb == 0) { cnt[rl][lane] = cnt[rs][lane]; continue; }
        unsigned a = cnt[rs][lane];
        unsigned b = cnt[rl][lane];
        unsigned same = __reduce_add_sync(FULLM, a * b);
        cnt[rl][lane] = (unsigned short)(a + b);
        if (lane == 0) {
            int e = (int)(v64 >> 42);
            w[e] = pos ? (float)same : (float)(sa * sb) - (float)same;
        }
    }

    // extra label chunks (rare: L > 32)
    for (int p = 1; p * 32 < L; p++) {
        unsigned* c32 = (unsigned*)cnt;
        for (int i = lane; i < NPX * 16; i += 32) c32[i] = 0;
        __syncwarp();
        for (int px = lane; px < NPX; px += 32) {
            int l = s->lab[px];
            if (l) {
                int c = (int)s->cid[l - 1] - p * 32;
                if (c >= 0 && c < 32) cnt[px][c] = 1;
            }
        }
        __syncwarp();
        for (int k = 0; k < nlog; k++) {
            unsigned long long v64 = lg[k];
            int sa = (int)(v64 & 0x7ffu);
            int sb = (int)((v64 >> 11) & 0x7ffu);
            int rs = (int)((v64 >> 22) & 0x3ffu);
            int rl = (int)((v64 >> 32) & 0x3ffu);
            if (sa == 0) continue;
            if (sb == 0) { cnt[rl][lane] = cnt[rs][lane]; continue; }
            unsigned a = cnt[rs][lane];
            unsigned b = cnt[rl][lane];
            unsigned same = __reduce_add_sync(FULLM, a * b);
            cnt[rl][lane] = (unsigned short)(a + b);
            if (lane == 0) {
                int e = (int)(v64 >> 42);
                if (pos) w[e] += (float)same;
                else     w[e] -= (float)same;
            }
        }
        __syncwarp();
    }
}

__device__ float block_reduce(Smem* s, float v) {
    int tid = threadIdx.x;
    s->red[tid] = v;
    __syncthreads();
    for (int off = NTHREADS / 2; off > 0; off >>= 1) {
        if (tid < off) s->red[tid] += s->red[tid + off];
        __syncthreads();
    }
    float r = s->red[0];
    __syncthreads();
    return r;
}

__global__ void __launch_bounds__(NTHREADS, 1)
zero_kernel(float* out, int n) {
    int i = blockIdx.x * blockDim.x + threadIdx.x;
    if (i < n) out[i] = 0.0f;
}

__global__ void __launch_bounds__(NTHREADS, 1)
malis_kernel(const float* __restrict__ pred,
             const float* __restrict__ target,
             const float* __restrict__ lrn_p,
             const float* __restrict__ lrp_p,
             float* __restrict__ out,
             int HW) {
    extern __shared__ char smem_raw[];
    Smem* s = (Smem*)smem_raw;
    const int tid = threadIdx.x;
    const int lane = tid & 31;

    int wpr = HW / WIN;
    int winPerImg = wpr * wpr;
    int b = blockIdx.x / winPerImg;
    int rem = blockIdx.x - b * winPerImg;
    int k = rem / wpr;
    int j = rem - k * wpr;
    int y0 = k * WIN, x0 = j * WIN;

    const float* pb = pred + (size_t)b * HW * HW;
    const float* tb = target + (size_t)b * HW * HW;

    // ---- 1. load tile; build zero-mask row bits via ballot ----
    for (int px = tid; px < NPX; px += NTHREADS) {
        int y = px >> 5, x = px & 31;
        float pv = pb[(y0 + y) * HW + (x0 + x)];
        float tv = tb[(y0 + y) * HW + (x0 + x)];
        s->pred[px] = pv;
        s->tvi[px] = (unsigned char)tv;            // ints 0..25, exact
        unsigned zb = __ballot_sync(FULLM, tv == 0.0f);
        if (lane == 0) s->rowmask[y] = zb;         // stride 256 => lane == x
    }
    __syncthreads();

    // ---- 2. dilate 5x in registers (warp 0, shfl across rows) ----
    if (tid < 32) {
        unsigned r = s->rowmask[tid];
        for (int it = 0; it < 5; it++) {
            unsigned up = __shfl_up_sync(FULLM, r, 1);
            unsigned dn = __shfl_down_sync(FULLM, r, 1);
            if (tid == 0) up = 0;
            if (tid == 31) dn = 0;
            r = r | (r << 1) | (r >> 1) | up | dn;
        }
        s->rowmask[tid] = r;
    }
    for (int px = tid; px < NPX; px += NTHREADS) s->par32[px] = (unsigned)px;
    __syncthreads();

    // ---- 3. 8-connected CC via lock-free union-find ----
    for (int px = tid; px < NPX; px += NTHREADS) {
        int y = px >> 5, x = px & 31;
        unsigned my = s->rowmask[y];
        if ((my >> x) & 1) continue;               // masked
        if (x < 31 && !((my >> (x + 1)) & 1)) cc_union(s->par32, px, px + 1);
        if (y < 31) {
            unsigned nx = s->rowmask[y + 1];
            if (!((nx >> x) & 1))                 cc_union(s->par32, px, px + 32);
            if (x < 31 && !((nx >> (x + 1)) & 1)) cc_union(s->par32, px, px + 33);
            if (x > 0  && !((nx >> (x - 1)) & 1)) cc_union(s->par32, px, px + 31);
        }
    }
    __syncthreads();
    for (int px = tid; px < NPX; px += NTHREADS) {
        int y = px >> 5, x = px & 31;
        unsigned my = s->rowmask[y];
        s->lab[px] = ((my >> x) & 1) ? 0
                   : (unsigned short)(cc_find(s->par32, px) + 1);
    }
    __syncthreads();

    // ---- 4. compact label ids ----
    for (int px = tid; px < NPX; px += NTHREADS) s->pres[px] = 0;
    __syncthreads();
    for (int px = tid; px < NPX; px += NTHREADS) {
        int l = s->lab[px];
        if (l) s->pres[l - 1] = 1;
    }
    __syncthreads();
    {
        int i0 = 4 * tid;
        int b0 = s->pres[i0], b1 = s->pres[i0 + 1];
        int b2 = s->pres[i0 + 2], b3 = s->pres[i0 + 3];
        int sum4 = b0 + b1 + b2 + b3;
        int incl = sum4;
        for (int off = 1; off < 32; off <<= 1) {
            int v = __shfl_up_sync(FULLM, incl, off);
            if (lane >= off) incl += v;
        }
        if (lane == 31) s->wsum[tid >> 5] = incl;
        __syncthreads();
        if (tid < 8) {
            int v = s->wsum[tid];
            int inc2 = v;
            for (int off = 1; off < 8; off <<= 1) {
                int t2 = __shfl_up_sync(0xffu, inc2, off);
                if (tid >= off) inc2 += t2;
            }
            s->wpre[tid] = inc2 - v;
            if (tid == 7) s->Lval = inc2;
        }
        __syncthreads();
        int pre = s->wpre[tid >> 5] + (incl - sum4);
        s->cid[i0]     = (unsigned short)pre;
        s->cid[i0 + 1] = (unsigned short)(pre + b0);
        s->cid[i0 + 2] = (unsigned short)(pre + b0 + b1);
        s->cid[i0 + 3] = (unsigned short)(pre + b0 + b1 + b2);
    }

    // ---- 5. edge flags, weight init, Kruskal union-find init ----
    for (int e = tid; e < NEDGE; e += NTHREADS) {
        int n1, n2;
        edge_nodes(e, n1, n2);
        int gtc = (int)s->tvi[n1] + (int)s->tvi[n2];
        unsigned char f = 0;
        if (gtc < 10)  f |= 1;
        if (gtc >= 20) f |= 2;
        if (gtc > 20)  f |= 4;
        s->eflags[e] = f;
        s->w0[e] = 0.0f;
        s->w1[e] = 0.0f;
    }
    for (int px = tid; px < NPX; px += NTHREADS) {
        unsigned short L = s->lab[px];
        unsigned stv = (1u << 16) | (L ? 1u : 0u);
        for (int r = 0; r < 2; r++) {
            s->parent[r][px] = (unsigned short)px;
            s->sizTot[r][px] = stv;
        }
    }
    if (tid < 2) s->logCnt[tid] = 0;
    __syncthreads();

    // ---- 6. two concurrent bitonic sorts (half-block each) ----
    {
        int half = tid >> 7;
        int t128 = tid & 127;
        int barid = half + 1;
        unsigned long long* sb = (unsigned long long*)(s->big[half]);
        for (int i = t128; i < SORTN; i += 128) {
            unsigned long long key;
            if (i < NEDGE) {
                int n1, n2;
                edge_nodes(i, n1, n2);
                float c;
                if (half == 0) {
                    c = s->pred[n1] + s->pred[n2];
                    if (s->eflags[i] & 4) c = 20.0f;
                } else {
                    c = (s->eflags[i] & 1) ? 0.0f
                                           : s->pred[n1] + s->pred[n2];
                }
                // nonneg floats: bit-monotone; ascending u64 =
                // descending cost, ties by ascending index.
                key = (((unsigned long long)(~__float_as_uint(c))) << 32)
                      | (unsigned)i;
            } else {
                key = ~0ULL;
            }
            sb[i] = key;
        }
        BARSYNC(barid);
        bitonic_sort_half(sb, t128, barid);
        unsigned short* ord = half ? s->order1 : s->order0;
        for (int i = t128; i < NEDGE; i += 128)
            ord[i] = (unsigned short)(sb[i] & 0xffffu);
    }
    __syncthreads();

    // ---- 7. zero cnt matrices (alias sortbuf) + scatter labeled pixels ----
    {
        unsigned* c32 = (unsigned*)s->big;
        for (int i = tid; i < 2 * 65536 / 4; i += NTHREADS) c32[i] = 0;
    }
    __syncthreads();
    {
        unsigned short (*c0)[32] = (unsigned short(*)[32])(s->big[0]);
        unsigned short (*c1)[32] = (unsigned short(*)[32])(s->big[1]);
        for (int px = tid; px < NPX; px += NTHREADS) {
            int l = s->lab[px];
            if (l) {
                int c = s->cid[l - 1];
                if (c < 32) { c0[px][c] = 1; c1[px][c] = 1; }
            }
        }
    }
    __syncthreads();

    // ---- 8. pipelined Kruskal (producers: warps 0,1) + replay (consumers: 2,3) ----
    {
        int wid = tid >> 5;
        int L = s->Lval;
        if      (wid == 0) kruskal_warp(s, 0, s->order0);
        else if (wid == 1) kruskal_warp(s, 1, s->order1);
        else if (wid == 2) replay_consumer(s, 0, L, false);
        else if (wid == 3) replay_consumer(s, 1, L, true);
    }
    __syncthreads();

    // ---- 9. normalize, mask, gather to nodes, loss ----
    float vn = 0.0f, vp = 0.0f;
    for (int e = tid; e < NEDGE; e += NTHREADS) {
        vn += s->w0[e];
        vp += s->w1[e];
    }
    float sn = block_reduce(s, vn);
    float sp = block_reduce(s, vp);

    for (int e = tid; e < NEDGE; e += NTHREADS) {
        unsigned char f = s->eflags[e];
        float a = s->w0[e];
        if (sn > 0.0f) a /= sn;
        s->w0[e] = (f & 1) ? a : 0.0f;
        float bb = s->w1[e];
        if (sp > 0.0f) bb /= sp;
        s->w1[e] = (f & 2) ? bb : 0.0f;
    }
    __syncthreads();

    float lrn = lrn_p[0];
    float lrp = lrp_p[0];
    float acc = 0.0f;
    for (int px = tid; px < NPX; px += NTHREADS) {
        int y = px >> 5, x = px & 31;
        float wn = 0.0f, wp = 0.0f;
        if (x > 0)  { int e = y * 31 + x - 1; wn += s->w0[e]; wp += s->w1[e]; }
        if (x < 31) { int e = y * 31 + x;     wn += s->w0[e]; wp += s->w1[e]; }
        if (y > 0)  { int e = NH + px - 32;   wn += s->w0[e]; wp += s->w1[e]; }
        if (y < 31) { int e = NH + px;        wn += s->w0[e]; wp += s->w1[e]; }
        float p = s->pred[px];
        float d = 20.0f - p;
        acc += lrn * p * p * wn + lrp * d * d * wp;
    }
    float total = block_reduce(s, acc);
    if (tid == 0) atomicAdd(out, total);
}

extern "C" void kernel_launch(void* const* d_in, const int* in_sizes, int n_in,
                              void* d_out, int out_size) {
    const float* pred   = (const float*)d_in[0];
    const float* target = (const float*)d_in[1];
    const float* lrn    = (const float*)d_in[2];
    const float* lrp    = (const float*)d_in[3];
    float* out = (float*)d_out;

    const int HW = 256;
    int B = in_sizes[0] / (HW * HW);
    int nblocks = B * (HW / WIN) * (HW / WIN);

    cudaFuncSetAttribute(malis_kernel,
                         cudaFuncAttributeMaxDynamicSharedMemorySize,
                         (int)sizeof(Smem));

    zero_kernel<<<(out_size + NTHREADS - 1) / NTHREADS, NTHREADS>>>(out, out_size);
    malis_kernel<<<nblocks, NTHREADS, sizeof(Smem)>>>(pred, target, lrn, lrp, out, HW);
}

// round 14
// speedup vs baseline: 1.0029x; 1.0005x over previous
#include <cuda_runtime.h>
#include <stdint.h>

#define WIN 32
#define NPX 1024
#define NH 992
#define NEDGE 1984
#define SORTN 2048
#define NTHREADS 256
#define FULLM 0xffffffffu
#define DONE_BIT (1 << 30)

#define BARSYNC(id) asm volatile("bar.sync %0, %1;" :: "r"(id), "r"(128) : "memory")

struct Smem {
    float pred[NPX];
    unsigned char tvi[NPX];
    unsigned rowmask[32];          // dilated mask bits, 1 = masked
    unsigned par32[NPX];           // CC labeling union-find (u32 for atomicCAS)
    unsigned short lab[NPX];
    unsigned char pres[NPX];
    unsigned short cid[NPX];
    unsigned char eflags[NEDGE];
    float w0[NEDGE];
    float w1[NEDGE];
    unsigned short order0[NEDGE];
    unsigned short order1[NEDGE];
    unsigned short parent[2][NPX];
    unsigned sizTot[2][NPX];       // (siz<<16) | tot, one load per root
    // packed merge log: sa | sb<<11 | rs<<22 | rl<<32 | e<<42
    unsigned long long mlog[2][NPX];
    unsigned batch[2][32];         // ra | rb<<10 | e<<20
    int logCnt[2];
    int Lval;
    int wsum[8];
    int wpre[8];
    float red[NTHREADS];
    // big[r]: sorts = u64 sortbuf (16KB of 64KB); replay = u16 cnt[NPX][32]
    alignas(16) unsigned char big[2][65536];
};

__device__ __forceinline__ void edge_nodes(int e, int& n1, int& n2) {
    if (e < NH) {
        int r = e / 31;
        int c = e - r * 31;
        n1 = (r << 5) + c;
        n2 = n1 + 1;
    } else {
        n1 = e - NH;
        n2 = n1 + 32;
    }
}

__device__ __forceinline__ int uf_find(unsigned short* par, int x) {
    while (par[x] != x) {
        par[x] = par[par[x]];
        x = par[x];
    }
    return x;
}

// ---- lock-free CC union-find (shared mem) ----
// Path-halving find: writes only par[x] = grandparent(x), NEVER writes to a
// root, so committed unions can never be resurrected by a racing find.
__device__ __forceinline__ unsigned cc_find(unsigned* par_, unsigned x) {
    volatile unsigned* par = par_;
    for (;;) {
        unsigned p = par[x];
        if (p == x) return x;
        unsigned g = par[p];
        if (g == p) return p;      // p is root
        par[x] = g;                // halve (g is an ancestor, g < x)
        x = g;
    }
}

__device__ __forceinline__ void cc_union(unsigned* par, unsigned a, unsigned b) {
    a = cc_find(par, a);
    b = cc_find(par, b);
    while (a != b) {
        if (a < b) { unsigned t = a; a = b; b = t; }   // ensure a > b
        unsigned old = atomicCAS(&par[a], a, b);
        if (old == a) return;
        a = cc_find(par, old);
        b = cc_find(par, b);
    }
}

// Bitonic sort over SORTN u64 keys with 128 threads; named barrier barid.
__device__ void bitonic_sort_half(unsigned long long* buf, int t, int barid) {
    for (int k = 2; k <= SORTN; k <<= 1) {
        for (int jj = k >> 1; jj > 0; jj >>= 1) {
            for (int i = t; i < SORTN; i += 128) {
                int p = i ^ jj;
                if (p > i) {
                    unsigned long long a = buf[i];
                    unsigned long long b = buf[p];
                    bool up = ((i & k) == 0);
                    if ((a > b) == up) { buf[i] = b; buf[p] = a; }
                }
            }
            BARSYNC(barid);
        }
    }
}

// Warp-cooperative speculative Kruskal (producer), shfl-free serial section.
// Per batch: 32 parallel finds -> dump (ra,rb,e) to smem -> lane 0 runs the
// serial merge loop with plain LDS loads and packed size/log entries.
__device__ void kruskal_warp(Smem* s, int run, const unsigned short* order) {
    unsigned short* par = s->parent[run];
    unsigned* st = s->sizTot[run];
    unsigned long long* lg = s->mlog[run];
    unsigned* batch = s->batch[run];
    volatile int* vc = &s->logCnt[run];

    const int lane = threadIdx.x & 31;
    int nlog = 0;

    for (int base = 0; base < NEDGE; base += 32) {
        int e = order[base + lane];
        int n1, n2;
        edge_nodes(e, n1, n2);
        int ra = uf_find(par, n1);
        int rb = uf_find(par, n2);
        // "connected in snapshot" is monotone => safe to drop those edges.
        unsigned alive = __ballot_sync(FULLM, ra != rb);
        batch[lane] = (unsigned)ra | ((unsigned)rb << 10) | ((unsigned)e << 20);
        __syncwarp();
        if (lane == 0 && alive) {
            // prefetch first entry
            int i = __ffs(alive) - 1;
            alive &= alive - 1;
            unsigned w = batch[i];
            for (;;) {
                unsigned wcur = w;
                bool more = (alive != 0);
                if (more) {                      // prefetch next entry
                    int i2 = __ffs(alive) - 1;
                    alive &= alive - 1;
                    w = batch[i2];
                }
                int rai = wcur & 1023;
                int rbi = (wcur >> 10) & 1023;
                int ei  = wcur >> 20;
                rai = uf_find(par, rai);         // short re-find (<=2 hops)
                rbi = uf_find(par, rbi);
                if (rai != rbi) {
                    unsigned pa = st[rai], pb = st[rbi];
                    int rs, rl;
                    unsigned ps, pl;
                    if ((pa >> 16) <= (pb >> 16)) { rs = rai; rl = rbi; ps = pa; pl = pb; }
                    else                          { rs = rbi; rl = rai; ps = pb; pl = pa; }
                    unsigned sa = ps & 0xffffu, sb = pl & 0xffffu;
                    par[rs] = (unsigned short)rl;
                    st[rl] = (((pa >> 16) + (pb >> 16)) << 16) | (sa + sb);
                    lg[nlog] = (unsigned long long)sa
                             | ((unsigned long long)sb << 11)
                             | ((unsigned long long)rs << 22)
                             | ((unsigned long long)rl << 32)
                             | ((unsigned long long)ei << 42);
                    nlog++;
                }
                if (!more) break;
            }
            __threadfence_block();
            *vc = nlog;                          // release publish
        }
        __syncwarp();
    }
    if (lane == 0) {
        __threadfence_block();
        *vc = nlog | DONE_BIT;
    }
}

// Streaming replay consumer (pass 0) + extra passes for L > 32.
__device__ void replay_consumer(Smem* s, int run, int L, bool pos) {
    const int lane = threadIdx.x & 31;
    unsigned short (*cnt)[32] = (unsigned short(*)[32])(s->big[run]);
    float* w = pos ? s->w1 : s->w0;
    volatile int* vc = &s->logCnt[run];
    unsigned long long* lg = s->mlog[run];

    int processed = 0, avail = 0;
    bool done = false;
    int nlog = 0;
    for (;;) {
        if (processed >= avail) {
            if (done) break;
            int v = *vc;                 // broadcast LDS
            int na = v & ~DONE_BIT;
            if (v & DONE_BIT) { done = true; nlog = na; }
            if (na > avail) {
                avail = na;
                __threadfence_block();   // acquire: order log reads after count
            }
            if (processed >= avail) {
                if (done) break;
                continue;
            }
        }
        int k = processed++;
        unsigned long long v64 = lg[k];  // one LDS.64 broadcast
        int sa = (int)(v64 & 0x7ffu);
        int sb = (int)((v64 >> 11) & 0x7ffu);
        int rs = (int)((v64 >> 22) & 0x3ffu);
        int rl = (int)((v64 >> 32) & 0x3ffu);
        if (sa == 0) continue;
        if (sb == 0) { cnt[rl][lane] = cnt[rs][lane]; continue; }
        unsigned a = cnt[rs][lane];
        unsigned b = cnt[rl][lane];
        unsigned same = __reduce_add_sync(FULLM, a * b);
        cnt[rl][lane] = (unsigned short)(a + b);
        if (lane == 0) {
            int e = (int)(v64 >> 42);
            w[e] = pos ? (float)same : (float)(sa * sb) - (float)same;
        }
    }

    // extra label chunks (rare: L > 32)
    for (int p = 1; p * 32 < L; p++) {
        unsigned* c32 = (unsigned*)cnt;
        for (int i = lane; i < NPX * 16; i += 32) c32[i] = 0;
        __syncwarp();
        for (int px = lane; px < NPX; px += 32) {
            int l = s->lab[px];
            if (l) {
                int c = (int)s->cid[l - 1] - p * 32;
                if (c >= 0 && c < 32) cnt[px][c] = 1;
            }
        }
        __syncwarp();
        for (int k = 0; k < nlog; k++) {
            unsigned long long v64 = lg[k];
            int sa = (int)(v64 & 0x7ffu);
            int sb = (int)((v64 >> 11) & 0x7ffu);
            int rs = (int)((v64 >> 22) & 0x3ffu);
            int rl = (int)((v64 >> 32) & 0x3ffu);
            if (sa == 0) continue;
            if (sb == 0) { cnt[rl][lane] = cnt[rs][lane]; continue; }
            unsigned a = cnt[rs][lane];
            unsigned b = cnt[rl][lane];
            unsigned same = __reduce_add_sync(FULLM, a * b);
            cnt[rl][lane] = (unsigned short)(a + b);
            if (lane == 0) {
                int e = (int)(v64 >> 42);
                if (pos) w[e] += (float)same;
                else     w[e] -= (float)same;
            }
        }
        __syncwarp();
    }
}

__device__ float block_reduce(Smem* s, float v) {
    int tid = threadIdx.x;
    s->red[tid] = v;
    __syncthreads();
    for (int off = NTHREADS / 2; off > 0; off >>= 1) {
        if (tid < off) s->red[tid] += s->red[tid + off];
        __syncthreads();
    }
    float r = s->red[0];
    __syncthreads();
    return r;
}

__global__ void __launch_bounds__(NTHREADS, 1)
zero_kernel(float* out, int n) {
    int i = blockIdx.x * blockDim.x + threadIdx.x;
    if (i < n) out[i] = 0.0f;
}

__global__ void __launch_bounds__(NTHREADS, 1)
malis_kernel(const float* __restrict__ pred,
             const float* __restrict__ target,
             const float* __restrict__ lrn_p,
             const float* __restrict__ lrp_p,
             float* __restrict__ out,
             int HW) {
    extern __shared__ char smem_raw[];
    Smem* s = (Smem*)smem_raw;
    const int tid = threadIdx.x;
    const int lane = tid & 31;

    int wpr = HW / WIN;
    int winPerImg = wpr * wpr;
    int b = blockIdx.x / winPerImg;
    int rem = blockIdx.x - b * winPerImg;
    int k = rem / wpr;
    int j = rem - k * wpr;
    int y0 = k * WIN, x0 = j * WIN;

    const float* pb = pred + (size_t)b * HW * HW;
    const float* tb = target + (size_t)b * HW * HW;

    // ---- 1. load tile; build zero-mask row bits via ballot ----
    for (int px = tid; px < NPX; px += NTHREADS) {
        int y = px >> 5, x = px & 31;
        float pv = pb[(y0 + y) * HW + (x0 + x)];
        float tv = tb[(y0 + y) * HW + (x0 + x)];
        s->pred[px] = pv;
        s->tvi[px] = (unsigned char)tv;            // ints 0..25, exact
        unsigned zb = __ballot_sync(FULLM, tv == 0.0f);
        if (lane == 0) s->rowmask[y] = zb;         // stride 256 => lane == x
    }
    __syncthreads();

    // ---- 2. dilate 5x in registers (warp 0, shfl across rows) ----
    if (tid < 32) {
        unsigned r = s->rowmask[tid];
        for (int it = 0; it < 5; it++) {
            unsigned up = __shfl_up_sync(FULLM, r, 1);
            unsigned dn = __shfl_down_sync(FULLM, r, 1);
            if (tid == 0) up = 0;
            if (tid == 31) dn = 0;
            r = r | (r << 1) | (r >> 1) | up | dn;
        }
        s->rowmask[tid] = r;
    }
    for (int px = tid; px < NPX; px += NTHREADS) s->par32[px] = (unsigned)px;
    __syncthreads();

    // ---- 3. 8-connected CC via lock-free union-find ----
    for (int px = tid; px < NPX; px += NTHREADS) {
        int y = px >> 5, x = px & 31;
        unsigned my = s->rowmask[y];
        if ((my >> x) & 1) continue;               // masked
        if (x < 31 && !((my >> (x + 1)) & 1)) cc_union(s->par32, px, px + 1);
        if (y < 31) {
            unsigned nx = s->rowmask[y + 1];
            if (!((nx >> x) & 1))                 cc_union(s->par32, px, px + 32);
            if (x < 31 && !((nx >> (x + 1)) & 1)) cc_union(s->par32, px, px + 33);
            if (x > 0  && !((nx >> (x - 1)) & 1)) cc_union(s->par32, px, px + 31);
        }
    }
    __syncthreads();
    for (int px = tid; px < NPX; px += NTHREADS) {
        int y = px >> 5, x = px & 31;
        unsigned my = s->rowmask[y];
        s->lab[px] = ((my >> x) & 1) ? 0
                   : (unsigned short)(cc_find(s->par32, px) + 1);
    }
    __syncthreads();

    // ---- 4. compact label ids ----
    for (int px = tid; px < NPX; px += NTHREADS) s->pres[px] = 0;
    __syncthreads();
    for (int px = tid; px < NPX; px += NTHREADS) {
        int l = s->lab[px];
        if (l) s->pres[l - 1] = 1;
    }
    __syncthreads();
    {
        int i0 = 4 * tid;
        int b0 = s->pres[i0], b1 = s->pres[i0 + 1];
        int b2 = s->pres[i0 + 2], b3 = s->pres[i0 + 3];
        int sum4 = b0 + b1 + b2 + b3;
        int incl = sum4;
        for (int off = 1; off < 32; off <<= 1) {
            int v = __shfl_up_sync(FULLM, incl, off);
            if (lane >= off) incl += v;
        }
        if (lane == 31) s->wsum[tid >> 5] = incl;
        __syncthreads();
        if (tid < 8) {
            int v = s->wsum[tid];
            int inc2 = v;
            for (int off = 1; off < 8; off <<= 1) {
                int t2 = __shfl_up_sync(0xffu, inc2, off);
                if (tid >= off) inc2 += t2;
            }
            s->wpre[tid] = inc2 - v;
            if (tid == 7) s->Lval = inc2;
        }
        __syncthreads();
        int pre = s->wpre[tid >> 5] + (incl - sum4);
        s->cid[i0]     = (unsigned short)pre;
        s->cid[i0 + 1] = (unsigned short)(pre + b0);
        s->cid[i0 + 2] = (unsigned short)(pre + b0 + b1);
        s->cid[i0 + 3] = (unsigned short)(pre + b0 + b1 + b2);
    }

    // ---- 5. edge flags, weight init, Kruskal union-find init ----
    for (int e = tid; e < NEDGE; e += NTHREADS) {
        int n1, n2;
        edge_nodes(e, n1, n2);
        int gtc = (int)s->tvi[n1] + (int)s->tvi[n2];
        unsigned char f = 0;
        if (gtc < 10)  f |= 1;
        if (gtc >= 20) f |= 2;
        if (gtc > 20)  f |= 4;
        s->eflags[e] = f;
        s->w0[e] = 0.0f;
        s->w1[e] = 0.0f;
    }
    for (int px = tid; px < NPX; px += NTHREADS) {
        unsigned short L = s->lab[px];
        unsigned stv = (1u << 16) | (L ? 1u : 0u);
        for (int r = 0; r < 2; r++) {
            s->parent[r][px] = (unsigned short)px;
            s->sizTot[r][px] = stv;
        }
    }
    if (tid < 2) s->logCnt[tid] = 0;
    __syncthreads();

    // ---- 6. two concurrent bitonic sorts (half-block each) ----
    {
        int half = tid >> 7;
        int t128 = tid & 127;
        int barid = half + 1;
        unsigned long long* sb = (unsigned long long*)(s->big[half]);
        for (int i = t128; i < SORTN; i += 128) {
            unsigned long long key;
            if (i < NEDGE) {
                int n1, n2;
                edge_nodes(i, n1, n2);
                float c;
                if (half == 0) {
                    c = s->pred[n1] + s->pred[n2];
                    if (s->eflags[i] & 4) c = 20.0f;
                } else {
                    c = (s->eflags[i] & 1) ? 0.0f
                                           : s->pred[n1] + s->pred[n2];
                }
                // nonneg floats: bit-monotone; ascending u64 =
                // descending cost, ties by ascending index.
                key = (((unsigned long long)(~__float_as_uint(c))) << 32)
                      | (unsigned)i;
            } else {
                key = ~0ULL;
            }
            sb[i] = key;
        }
        BARSYNC(barid);
        bitonic_sort_half(sb, t128, barid);
        unsigned short* ord = half ? s->order1 : s->order0;
        for (int i = t128; i < NEDGE; i += 128)
            ord[i] = (unsigned short)(sb[i] & 0xffffu);
    }
    __syncthreads();

    // ---- 7. zero cnt matrices (alias sortbuf) + scatter labeled pixels ----
    {
        unsigned* c32 = (unsigned*)s->big;
        for (int i = tid; i < 2 * 65536 / 4; i += NTHREADS) c32[i] = 0;
    }
    __syncthreads();
    {
        unsigned short (*c0)[32] = (unsigned short(*)[32])(s->big[0]);
        unsigned short (*c1)[32] = (unsigned short(*)[32])(s->big[1]);
        for (int px = tid; px < NPX; px += NTHREADS) {
            int l = s->lab[px];
            if (l) {
                int c = s->cid[l - 1];
                if (c < 32) { c0[px][c] = 1; c1[px][c] = 1; }
            }
        }
    }
    __syncthreads();

    // ---- 8. pipelined Kruskal (producers: warps 0,1) + replay (consumers: 2,3) ----
    {
        int wid = tid >> 5;
        int L = s->Lval;
        if      (wid == 0) kruskal_warp(s, 0, s->order0);
        else if (wid == 1) kruskal_warp(s, 1, s->order1);
        else if (wid == 2) replay_consumer(s, 0, L, false);
        else if (wid == 3) replay_consumer(s, 1, L, true);
    }
    __syncthreads();

    // ---- 9. normalize, mask, gather to nodes, loss ----
    float vn = 0.0f, vp = 0.0f;
    for (int e = tid; e < NEDGE; e += NTHREADS) {
        vn += s->w0[e];
        vp += s->w1[e];
    }
    float sn = block_reduce(s, vn);
    float sp = block_reduce(s, vp);

    for (int e = tid; e < NEDGE; e += NTHREADS) {
        unsigned char f = s->eflags[e];
        float a = s->w0[e];
        if (sn > 0.0f) a /= sn;
        s->w0[e] = (f & 1) ? a : 0.0f;
        float bb = s->w1[e];
        if (sp > 0.0f) bb /= sp;
        s->w1[e] = (f & 2) ? bb : 0.0f;
    }
    __syncthreads();

    float lrn = lrn_p[0];
    float lrp = lrp_p[0];
    float acc = 0.0f;
    for (int px = tid; px < NPX; px += NTHREADS) {
        int y = px >> 5, x = px & 31;
        float wn = 0.0f, wp = 0.0f;
        if (x > 0)  { int e = y * 31 + x - 1; wn += s->w0[e]; wp += s->w1[e]; }
        if (x < 31) { int e = y * 31 + x;     wn += s->w0[e]; wp += s->w1[e]; }
        if (y > 0)  { int e = NH + px - 32;   wn += s->w0[e]; wp += s->w1[e]; }
        if (y < 31) { int e = NH + px;        wn += s->w0[e]; wp += s->w1[e]; }
        float p = s->pred[px];
        float d = 20.0f - p;
        acc += lrn * p * p * wn + lrp * d * d * wp;
    }
    float total = block_reduce(s, acc);
    if (tid == 0) atomicAdd(out, total);
}

extern "C" void kernel_launch(void* const* d_in, const int* in_sizes, int n_in,
                              void* d_out, int out_size) {
    const float* pred   = (const float*)d_in[0];
    const float* target = (const float*)d_in[1];
    const float* lrn    = (const float*)d_in[2];
    const float* lrp    = (const float*)d_in[3];
    float* out = (float*)d_out;

    const int HW = 256;
    int B = in_sizes[0] / (HW * HW);
    int nblocks = B * (HW / WIN) * (HW / WIN);

    cudaFuncSetAttribute(malis_kernel,
                         cudaFuncAttributeMaxDynamicSharedMemorySize,
                         (int)sizeof(Smem));

    zero_kernel<<<(out_size + NTHREADS - 1) / NTHREADS, NTHREADS>>>(out, out_size);
    malis_kernel<<<nblocks, NTHREADS, sizeof(Smem)>>>(pred, target, lrn, lrp, out, HW);
}